// round 15
// baseline (speedup 1.0000x reference)
#include <cuda_runtime.h>
#include <math.h>

// Scratch (device globals; no allocation allowed)
__device__ float g_S  [64];              // row sums of x
__device__ float g_u  [64 * 256];        // u[b,h] = sum_i x[b,i]*h[b,i,h]

__device__ __forceinline__ float tanh_fast(float v) {
    float y;
    asm("tanh.approx.f32 %0, %1;" : "=f"(y) : "f"(v));
    return y;
}

// ---------------------------------------------------------------------------
// K2': u[b,h] = sum_{r,j} x[b, r*32+j] * tanh(A[j,h] + C[r,h])
//   A[j,h] = pos_enc(j) @ W1[0:64, h]   + x-chunk_j @ W1[128:160, h]
//   C[r,h] = pos_enc(r) @ W1[64:128, h] + b1[h]
// All computed in-block: W1 slice (160 x 32) staged in smem, pe table built
// with sincosf. Blocks with hc==0 also emit S[b] = sum_i x[b,i].
// grid 512 blocks: (b, h-chunk of 32). 256 threads.
// ---------------------------------------------------------------------------
__global__ void __launch_bounds__(256) k2_u(
        const float* __restrict__ x,
        const float* __restrict__ W1,
        const float* __restrict__ b1) {
    int b = blockIdx.x >> 3;
    int hc = blockIdx.x & 7;
    int t = threadIdx.x;
    int hl = t & 31;
    int rg = t >> 5;
    int h = hc * 32 + hl;

    __shared__ float xs[1024];
    __shared__ float W1s[160][33];
    __shared__ float pes[32][64];
    __shared__ float As[32][33];
    __shared__ float Cs[32][33];

    for (int i = t; i < 1024; i += 256) xs[i] = x[b * 1024 + i];
    // stage full W1 column-chunk: 160 rows x 32 cols, coalesced
#pragma unroll
    for (int q = 0; q < 20; q++) {
        int i = t + q * 256;
        int r = i >> 5, c = i & 31;
        W1s[r][c] = W1[r * 256 + hc * 32 + c];
    }
    // pe table: (pos,k) pairs, 4 per thread
#pragma unroll
    for (int q = 0; q < 4; q++) {
        int pi = t + q * 256;
        int pos = pi >> 5, k = pi & 31;
        float e = -(2.0f * (float)k) * (13.2877123795494f / 64.0f);
        float invf = exp2f(e);
        float ang = (float)pos * invf;
        float s, c;
        sincosf(ang, &s, &c);
        pes[pos][2 * k] = s;
        pes[pos][2 * k + 1] = c;
    }
    __syncthreads();

    float b1v = b1[h];

    // A and C entries: thread (rg, hl) handles indices rg*4 .. rg*4+3
#pragma unroll
    for (int q = 0; q < 4; q++) {
        int j = rg * 4 + q;
        float a = 0.f;
        const float4* p4 = (const float4*)&pes[j][0];
#pragma unroll
        for (int d4 = 0; d4 < 16; d4++) {
            float4 pv = p4[d4];
            a = fmaf(pv.x, W1s[d4 * 4 + 0][hl], a);
            a = fmaf(pv.y, W1s[d4 * 4 + 1][hl], a);
            a = fmaf(pv.z, W1s[d4 * 4 + 2][hl], a);
            a = fmaf(pv.w, W1s[d4 * 4 + 3][hl], a);
        }
        const float* xj = &xs[j * 32];
#pragma unroll
        for (int c = 0; c < 32; c++)
            a = fmaf(xj[c], W1s[128 + c][hl], a);
        As[j][hl] = a;

        float cc = b1v;
#pragma unroll
        for (int d4 = 0; d4 < 16; d4++) {
            float4 pv = p4[d4];
            cc = fmaf(pv.x, W1s[64 + d4 * 4 + 0][hl], cc);
            cc = fmaf(pv.y, W1s[64 + d4 * 4 + 1][hl], cc);
            cc = fmaf(pv.z, W1s[64 + d4 * 4 + 2][hl], cc);
            cc = fmaf(pv.w, W1s[64 + d4 * 4 + 3][hl], cc);
        }
        Cs[j][hl] = cc;
    }

    // S[b] from staged xs (hc==0 blocks only)
    __shared__ float sred[8];
    if (hc == 0) {
        float s = 0.f;
        for (int i = t; i < 1024; i += 256) s += xs[i];
#pragma unroll
        for (int off = 16; off > 0; off >>= 1)
            s += __shfl_xor_sync(0xffffffffu, s, off);
        if ((t & 31) == 0) sred[t >> 5] = s;
    }
    __syncthreads();

    if (hc == 0 && t == 0) {
        float tot = 0.f;
#pragma unroll
        for (int p = 0; p < 8; p++) tot += sred[p];
        g_S[b] = tot;
    }

    float A[32];
#pragma unroll
    for (int j = 0; j < 32; j++) A[j] = As[j][hl];

    float acc = 0.f;
#pragma unroll
    for (int rr = 0; rr < 4; rr++) {
        int r = rg * 4 + rr;
        float C = Cs[r][hl];
        const float* xr = &xs[r * 32];
#pragma unroll
        for (int j = 0; j < 32; j++)
            acc = fmaf(xr[j], tanh_fast(A[j] + C), acc);
    }

    __shared__ float red[8][33];
    red[rg][hl] = acc;
    __syncthreads();
    if (t < 32) {
        float s = 0.f;
#pragma unroll
        for (int p = 0; p < 8; p++) s += red[p][t];
        g_u[b * 256 + hc * 32 + t] = s;
    }
}

// ---------------------------------------------------------------------------
// K34': fused einsum-output + bias hypernetwork + final add; PEB computed
// in-block (2 rows per block).
// grid 256 blocks: bg (4 batches) x oc (64-output chunk). 256 threads.
// ---------------------------------------------------------------------------
__global__ void __launch_bounds__(256) k34_fused(
        const float* __restrict__ W2,
        const float* __restrict__ b2,
        const float* __restrict__ Wb1,
        const float* __restrict__ bb1,
        const float* __restrict__ Wb2,
        const float* __restrict__ bb2,
        float* __restrict__ y) {
    int bg = blockIdx.x >> 4;     // 0..15 (4 batches each)
    int oc = blockIdx.x & 15;     // 0..15 (64-output chunk)
    int t = threadIdx.x;

    __shared__ float buf[4096];   // 16KB, aliased between phases
    __shared__ float os[8][32];   // out values: row = bb*2+cc
    __shared__ float Ss[4];
    __shared__ float peb_tab[2][64];
    __shared__ float pebs[2][256];

    // ---- Phase A: out = u @ W2 + S*b2 ----
    float* us   = buf;            // [256][4]  u transposed
    float* red4 = buf + 1024;     // [4][4][64]

    int ol = t & 63;
    int hg4 = t >> 6;             // 0..3
    int o = oc * 64 + ol;

    for (int i = t; i < 256 * 4; i += 256) {
        int h = i >> 2, bb = i & 3;
        us[h * 4 + bb] = g_u[(bg * 4 + bb) * 256 + h];
    }
    if (t < 4) Ss[t] = g_S[bg * 4 + t];

    // pe table for the 2 bias positions of this block
    if (t < 64) {
        int pos = oc * 2 + (t >> 5);
        int k = t & 31;
        float e = -(2.0f * (float)k) * (13.2877123795494f / 64.0f);
        float invf = exp2f(e);
        float ang = (float)pos * invf;
        float s, c;
        sincosf(ang, &s, &c);
        peb_tab[t >> 5][2 * k] = s;
        peb_tab[t >> 5][2 * k + 1] = c;
    }

    // preload phase-B weights (overlaps with phase A latency)
    int hg = t >> 5, m = t & 31;
    float w1[32], w2[32];
#pragma unroll
    for (int k = 0; k < 32; k++) w1[k] = Wb1[k * 256 + t];
#pragma unroll
    for (int hh = 0; hh < 32; hh++) w2[hh] = Wb2[(hg * 32 + hh) * 32 + m];

    __syncthreads();

    float acc[4] = {0.f, 0.f, 0.f, 0.f};
#pragma unroll 8
    for (int hh = 0; hh < 64; hh++) {
        int h = hg4 * 64 + hh;
        float w = W2[h * 1024 + o];
        const float* uh = &us[h * 4];
#pragma unroll
        for (int bb = 0; bb < 4; bb++)
            acc[bb] = fmaf(uh[bb], w, acc[bb]);
    }
#pragma unroll
    for (int bb = 0; bb < 4; bb++)
        red4[(hg4 * 4 + bb) * 64 + ol] = acc[bb];

    // PEB rows: a_r = bb1[t] + sum_d peb_tab[r][d] * Wb1[(32+d)*256 + t]
    {
        float a0 = bb1[t], a1 = a0;
#pragma unroll 16
        for (int d = 0; d < 64; d++) {
            float wv = Wb1[(32 + d) * 256 + t];
            a0 = fmaf(peb_tab[0][d], wv, a0);
            a1 = fmaf(peb_tab[1][d], wv, a1);
        }
        pebs[0][t] = a0;
        pebs[1][t] = a1;
    }
    __syncthreads();

    {
        int bb = t >> 6;          // 0..3
        float s = red4[(0 * 4 + bb) * 64 + ol] + red4[(1 * 4 + bb) * 64 + ol]
                + red4[(2 * 4 + bb) * 64 + ol] + red4[(3 * 4 + bb) * 64 + ol];
        s = fmaf(Ss[bb], b2[o], s);
        os[bb * 2 + (ol >> 5)][ol & 31] = s;
    }
    __syncthreads();

    // ---- Phase B: bias hypernetwork over 8 rows ----
    float* H    = buf;            // [8][256]
    float* red8 = buf + 2048;     // [8][8][32]

#pragma unroll
    for (int r = 0; r < 8; r++) {
        float a = pebs[r & 1][t];
        const float4* o4 = (const float4*)os[r];
#pragma unroll
        for (int q = 0; q < 8; q++) {
            float4 ov = o4[q];
            a = fmaf(ov.x, w1[4 * q + 0], a);
            a = fmaf(ov.y, w1[4 * q + 1], a);
            a = fmaf(ov.z, w1[4 * q + 2], a);
            a = fmaf(ov.w, w1[4 * q + 3], a);
        }
        H[r * 256 + t] = tanh_fast(a);
    }
    __syncthreads();

#pragma unroll
    for (int r = 0; r < 8; r++) {
        float s = 0.f;
        const float4* h4 = (const float4*)&H[r * 256 + hg * 32];
#pragma unroll
        for (int q = 0; q < 8; q++) {
            float4 hv = h4[q];
            s = fmaf(hv.x, w2[4 * q + 0], s);
            s = fmaf(hv.y, w2[4 * q + 1], s);
            s = fmaf(hv.z, w2[4 * q + 2], s);
            s = fmaf(hv.w, w2[4 * q + 3], s);
        }
        red8[(hg * 8 + r) * 32 + m] = s;
    }
    __syncthreads();

    // Final: 8 rows x 32 outputs = 256 values, 1 per thread
    {
        int r = t >> 5, mm = t & 31;
        float bias = bb2[mm];
#pragma unroll
        for (int p = 0; p < 8; p++) bias += red8[(p * 8 + r) * 32 + mm];
        int bb = r >> 1, cc = r & 1;
        y[(bg * 4 + bb) * 1024 + oc * 64 + cc * 32 + mm] = os[r][mm] + bias;
    }
}

extern "C" void kernel_launch(void* const* d_in, const int* in_sizes, int n_in,
                              void* d_out, int out_size) {
    const float* x   = (const float*)d_in[0];
    // d_in[1] = output_size (int) — fixed at 1024 by the problem shapes
    const float* W1  = (const float*)d_in[2];
    const float* b1  = (const float*)d_in[3];
    const float* W2  = (const float*)d_in[4];
    const float* b2  = (const float*)d_in[5];
    const float* Wb1 = (const float*)d_in[6];
    const float* bb1 = (const float*)d_in[7];
    const float* Wb2 = (const float*)d_in[8];
    const float* bb2 = (const float*)d_in[9];
    float* y = (float*)d_out;

    k2_u<<<512, 256>>>(x, W1, b1);
    k34_fused<<<256, 256>>>(W2, b2, Wb1, bb1, Wb2, bb2, y);
}